// round 3
// baseline (speedup 1.0000x reference)
#include <cuda_runtime.h>
#include <cuda_bf16.h>
#include <mma.h>

using namespace nvcuda;

#define NP 8
#define HD 1024
#define BD 2048

// ---------------- device scratch (module globals; no runtime alloc) ----------------
__device__ float g_v[NP];    // (1-alpha)*u[j]  -> folded into W_eff
__device__ float g_cw[NP];   // alpha*u[j]      -> coherent weights

__device__ __nv_bfloat16 g_Wi_hi[HD * HD];
__device__ __nv_bfloat16 g_Wi_lo[HD * HD];
__device__ __nv_bfloat16 g_We_hi[HD * HD];
__device__ __nv_bfloat16 g_We_lo[HD * HD];
__device__ float         g_M[HD * HD];
__device__ __nv_bfloat16 g_M_hi[HD * HD];
__device__ __nv_bfloat16 g_M_lo[HD * HD];
__device__ __nv_bfloat16 g_x_hi[BD * HD];
__device__ __nv_bfloat16 g_x_lo[BD * HD];
__device__ float         g_T[BD * HD];

// ---------------- kernel 1: scalars (alpha, interference colsums) ----------------
__global__ void prep_kernel(const float* __restrict__ J, const float* __restrict__ t_ptr) {
    if (threadIdx.x != 0) return;
    const float t = t_ptr[0];
    float alpha = expf(-t / 51.0f);                 // T2_EFF = 51.0
    alpha = fminf(fmaxf(alpha, 0.0f), 1.0f);
    const float phase = 2.0f * 3.14159265358979323846f * 20.0f * t / 1000.0f;

    float colsum[NP];
#pragma unroll
    for (int j = 0; j < NP; j++) colsum[j] = 0.0f;

    for (int i = 0; i < NP; i++) {
        float row[NP];
        float mx = -1e30f;
#pragma unroll
        for (int j = 0; j < NP; j++) {
            float js = 0.5f * (J[i * NP + j] + J[j * NP + i]);
            row[j] = cosf(phase * js);
            mx = fmaxf(mx, row[j]);
        }
        float s = 0.0f;
#pragma unroll
        for (int j = 0; j < NP; j++) { row[j] = expf(row[j] - mx); s += row[j]; }
        float inv_s = 1.0f / s;
#pragma unroll
        for (int j = 0; j < NP; j++) colsum[j] += row[j] * inv_s;
    }
    const float scale = alpha / (float)(NP * NP);   // alpha / 64
#pragma unroll
    for (int j = 0; j < NP; j++) {
        float u = scale * colsum[j];
        g_v[j]  = (1.0f - alpha) * u;
        g_cw[j] = alpha * u;
    }
}

// ---------------- kernel 2: W_eff = sum_j v[j]*W_paths[j], split; also split W_input ----------------
__global__ void build_weff_kernel(const float* __restrict__ Wp, const float* __restrict__ Wi) {
    const int idx = blockIdx.x * blockDim.x + threadIdx.x;   // 0 .. HD*HD-1
    float s = 0.0f;
#pragma unroll
    for (int j = 0; j < NP; j++) s = fmaf(g_v[j], Wp[(size_t)j * (HD * HD) + idx], s);
    __nv_bfloat16 hi = __float2bfloat16(s);
    g_We_hi[idx] = hi;
    g_We_lo[idx] = __float2bfloat16(s - __bfloat162float(hi));

    float wv = Wi[idx];
    hi = __float2bfloat16(wv);
    g_Wi_hi[idx] = hi;
    g_Wi_lo[idx] = __float2bfloat16(wv - __bfloat162float(hi));
}

// ---------------- kernel 3: split x into bf16 hi/lo ----------------
__global__ void split_x_kernel(const float* __restrict__ x) {
    const int idx = blockIdx.x * blockDim.x + threadIdx.x;   // 0 .. BD*HD-1
    float v = x[idx];
    __nv_bfloat16 hi = __float2bfloat16(v);
    g_x_hi[idx] = hi;
    g_x_lo[idx] = __float2bfloat16(v - __bfloat162float(hi));
}

// ---------------- split M after first GEMM ----------------
__global__ void split_M_kernel() {
    const int idx = blockIdx.x * blockDim.x + threadIdx.x;   // 0 .. HD*HD-1
    float v = g_M[idx];
    __nv_bfloat16 hi = __float2bfloat16(v);
    g_M_hi[idx] = hi;
    g_M_lo[idx] = __float2bfloat16(v - __bfloat162float(hi));
}

// ---------------- bf16x3 GEMM body: C[M,N] = (Ah+Al) @ (Bh+Bl), fp32 accum ----------------
// Tiles: BM=128, BN=64, BK=32; 256 threads = 8 warps laid out 4(m) x 2(n),
// each warp owns a 32x32 output region = 2x2 wmma m16n16k16 tiles.
__device__ __forceinline__ void gemm_body(
    const __nv_bfloat16* __restrict__ Ah, const __nv_bfloat16* __restrict__ Al,
    const __nv_bfloat16* __restrict__ Bh, const __nv_bfloat16* __restrict__ Bl,
    float* __restrict__ C, int Mdim, int Ndim, int Kdim)
{
    __shared__ __align__(16) __nv_bfloat16 sAh[128][48];
    __shared__ __align__(16) __nv_bfloat16 sAl[128][48];
    __shared__ __align__(16) __nv_bfloat16 sBh[32][80];
    __shared__ __align__(16) __nv_bfloat16 sBl[32][80];

    const int tid    = threadIdx.x;
    const int wid    = tid >> 5;
    const int warp_m = wid & 3;       // 0..3 -> 32-row strip
    const int warp_n = wid >> 2;      // 0..1 -> 32-col strip
    const int mBase  = blockIdx.y * 128;
    const int nBase  = blockIdx.x * 64;

    wmma::fragment<wmma::accumulator, 16, 16, 16, float> acc[2][2];
#pragma unroll
    for (int i = 0; i < 2; i++)
#pragma unroll
        for (int j = 0; j < 2; j++) wmma::fill_fragment(acc[i][j], 0.0f);

    for (int k0 = 0; k0 < Kdim; k0 += 32) {
        // A tile: 128 rows x 32 cols bf16 => 512 uint4; 2 per thread per array
#pragma unroll
        for (int it = 0; it < 2; ++it) {
            int u = tid + it * 256;
            int r = u >> 2, c = u & 3;
            const uint4* gh = (const uint4*)(Ah + (size_t)(mBase + r) * Kdim + k0) + c;
            const uint4* gl = (const uint4*)(Al + (size_t)(mBase + r) * Kdim + k0) + c;
            *(uint4*)(&sAh[r][c * 8]) = *gh;
            *(uint4*)(&sAl[r][c * 8]) = *gl;
        }
        // B tile: 32 rows x 64 cols bf16 => 256 uint4; 1 per thread per array
        {
            int r = tid >> 3, c = tid & 7;
            const uint4* gh = (const uint4*)(Bh + (size_t)(k0 + r) * Ndim + nBase) + c;
            const uint4* gl = (const uint4*)(Bl + (size_t)(k0 + r) * Ndim + nBase) + c;
            *(uint4*)(&sBh[r][c * 8]) = *gh;
            *(uint4*)(&sBl[r][c * 8]) = *gl;
        }
        __syncthreads();

#pragma unroll
        for (int kc = 0; kc < 2; kc++) {
            wmma::fragment<wmma::matrix_a, 16, 16, 16, __nv_bfloat16, wmma::row_major> ah[2], al[2];
            wmma::fragment<wmma::matrix_b, 16, 16, 16, __nv_bfloat16, wmma::row_major> bh[2], bl[2];
#pragma unroll
            for (int mi = 0; mi < 2; mi++) {
                wmma::load_matrix_sync(ah[mi], &sAh[warp_m * 32 + mi * 16][kc * 16], 48);
                wmma::load_matrix_sync(al[mi], &sAl[warp_m * 32 + mi * 16][kc * 16], 48);
            }
#pragma unroll
            for (int ni = 0; ni < 2; ni++) {
                wmma::load_matrix_sync(bh[ni], &sBh[kc * 16][warp_n * 32 + ni * 16], 80);
                wmma::load_matrix_sync(bl[ni], &sBl[kc * 16][warp_n * 32 + ni * 16], 80);
            }
#pragma unroll
            for (int mi = 0; mi < 2; mi++)
#pragma unroll
                for (int ni = 0; ni < 2; ni++) {
                    wmma::mma_sync(acc[mi][ni], ah[mi], bh[ni], acc[mi][ni]);  // hi*hi
                    wmma::mma_sync(acc[mi][ni], ah[mi], bl[ni], acc[mi][ni]);  // hi*lo
                    wmma::mma_sync(acc[mi][ni], al[mi], bh[ni], acc[mi][ni]);  // lo*hi
                }
        }
        __syncthreads();
    }

#pragma unroll
    for (int mi = 0; mi < 2; mi++)
#pragma unroll
        for (int ni = 0; ni < 2; ni++) {
            float* cp = C + (size_t)(mBase + warp_m * 32 + mi * 16) * Ndim
                          + nBase + warp_n * 32 + ni * 16;
            wmma::store_matrix_sync(cp, acc[mi][ni], Ndim, wmma::mem_row_major);
        }
}

// GEMM 1: M = W_input @ W_eff   (1024 x 1024 x 1024)
__global__ void gemm1_kernel() {
    gemm_body(g_Wi_hi, g_Wi_lo, g_We_hi, g_We_lo, g_M, HD, HD, HD);
}

// GEMM 2: T = x @ M             (2048 x 1024 x 1024)
__global__ void gemm2_kernel() {
    gemm_body(g_x_hi, g_x_lo, g_M_hi, g_M_lo, g_T, BD, HD, HD);
}

// ---------------- final epilogue: out = T + sum_j cw[j]*coh[:,j,:] ----------------
__global__ void epilogue_kernel(const float* __restrict__ coh, float* __restrict__ out) {
    const int idx = blockIdx.x * blockDim.x + threadIdx.x;   // handles 4 floats
    const int e = idx * 4;
    const int b = e >> 10;
    const int h = e & 1023;
    float4 acc = *(const float4*)&g_T[e];
#pragma unroll
    for (int j = 0; j < NP; j++) {
        const float4 c = *(const float4*)&coh[((size_t)b * NP + j) * HD + h];
        const float w = g_cw[j];
        acc.x = fmaf(w, c.x, acc.x);
        acc.y = fmaf(w, c.y, acc.y);
        acc.z = fmaf(w, c.z, acc.z);
        acc.w = fmaf(w, c.w, acc.w);
    }
    *(float4*)&out[e] = acc;
}

// ---------------- launch ----------------
extern "C" void kernel_launch(void* const* d_in, const int* in_sizes, int n_in,
                              void* d_out, int out_size) {
    (void)in_sizes; (void)n_in; (void)out_size;
    const float* x   = (const float*)d_in[0];
    const float* Wi  = (const float*)d_in[1];
    const float* Wp  = (const float*)d_in[2];
    const float* J   = (const float*)d_in[3];
    const float* coh = (const float*)d_in[4];
    const float* t   = (const float*)d_in[5];
    float* out = (float*)d_out;

    prep_kernel<<<1, 32>>>(J, t);
    build_weff_kernel<<<(HD * HD) / 256, 256>>>(Wp, Wi);
    split_x_kernel<<<(BD * HD) / 256, 256>>>(x);

    {
        dim3 g(HD / 64, HD / 128);
        gemm1_kernel<<<g, 256>>>();
    }
    split_M_kernel<<<(HD * HD) / 256, 256>>>();
    {
        dim3 g(HD / 64, BD / 128);
        gemm2_kernel<<<g, 256>>>();
    }
    epilogue_kernel<<<(BD * HD / 4) / 256, 256>>>(coh, out);
}

// round 5
// speedup vs baseline: 1.0374x; 1.0374x over previous
#include <cuda_runtime.h>
#include <cuda_bf16.h>
#include <mma.h>

using namespace nvcuda;

#define NP 8
#define HD 1024
#define BD 2048
#define BM 128
#define BK 16

// ---------------- device scratch ----------------
__device__ float g_v[NP];    // (1-alpha)*u[j]
__device__ float g_cw[NP];   // alpha*u[j]

__device__ __nv_bfloat16 g_Wi_hi[HD * HD];
__device__ __nv_bfloat16 g_Wi_lo[HD * HD];
__device__ __nv_bfloat16 g_We_hi[HD * HD];
__device__ __nv_bfloat16 g_We_lo[HD * HD];
__device__ __nv_bfloat16 g_M_hi[HD * HD];
__device__ __nv_bfloat16 g_M_lo[HD * HD];
__device__ __nv_bfloat16 g_x_hi[BD * HD];
__device__ __nv_bfloat16 g_x_lo[BD * HD];

// ---------------- kernel 1: scalars ----------------
__global__ void prep_kernel(const float* __restrict__ J, const float* __restrict__ t_ptr) {
    if (threadIdx.x != 0) return;
    const float t = t_ptr[0];
    float alpha = expf(-t / 51.0f);
    alpha = fminf(fmaxf(alpha, 0.0f), 1.0f);
    const float phase = 2.0f * 3.14159265358979323846f * 20.0f * t / 1000.0f;

    float colsum[NP];
#pragma unroll
    for (int j = 0; j < NP; j++) colsum[j] = 0.0f;

    for (int i = 0; i < NP; i++) {
        float row[NP];
        float mx = -1e30f;
#pragma unroll
        for (int j = 0; j < NP; j++) {
            float js = 0.5f * (J[i * NP + j] + J[j * NP + i]);
            row[j] = cosf(phase * js);
            mx = fmaxf(mx, row[j]);
        }
        float s = 0.0f;
#pragma unroll
        for (int j = 0; j < NP; j++) { row[j] = expf(row[j] - mx); s += row[j]; }
        float inv_s = 1.0f / s;
#pragma unroll
        for (int j = 0; j < NP; j++) colsum[j] += row[j] * inv_s;
    }
    const float scale = alpha / (float)(NP * NP);
#pragma unroll
    for (int j = 0; j < NP; j++) {
        float u = scale * colsum[j];
        g_v[j]  = (1.0f - alpha) * u;
        g_cw[j] = alpha * u;
    }
}

// ---------------- kernel 2: W_eff build + split (float4 vectorized) ----------------
__global__ void build_weff_kernel(const float* __restrict__ Wp, const float* __restrict__ Wi) {
    const int e = (blockIdx.x * blockDim.x + threadIdx.x) * 4;   // 0 .. HD*HD-1 by 4
    float4 s = make_float4(0.f, 0.f, 0.f, 0.f);
#pragma unroll
    for (int j = 0; j < NP; j++) {
        const float4 w = *(const float4*)&Wp[(size_t)j * (HD * HD) + e];
        const float v = g_v[j];
        s.x = fmaf(v, w.x, s.x); s.y = fmaf(v, w.y, s.y);
        s.z = fmaf(v, w.z, s.z); s.w = fmaf(v, w.w, s.w);
    }
    __nv_bfloat16 hi[4], lo[4];
    float sv[4] = {s.x, s.y, s.z, s.w};
#pragma unroll
    for (int i = 0; i < 4; i++) {
        hi[i] = __float2bfloat16(sv[i]);
        lo[i] = __float2bfloat16(sv[i] - __bfloat162float(hi[i]));
    }
    *(uint2*)&g_We_hi[e] = *(uint2*)hi;
    *(uint2*)&g_We_lo[e] = *(uint2*)lo;

    const float4 w = *(const float4*)&Wi[e];
    float wv[4] = {w.x, w.y, w.z, w.w};
#pragma unroll
    for (int i = 0; i < 4; i++) {
        hi[i] = __float2bfloat16(wv[i]);
        lo[i] = __float2bfloat16(wv[i] - __bfloat162float(hi[i]));
    }
    *(uint2*)&g_Wi_hi[e] = *(uint2*)hi;
    *(uint2*)&g_Wi_lo[e] = *(uint2*)lo;
}

// ---------------- kernel 3: split x (float4 vectorized) ----------------
__global__ void split_x_kernel(const float* __restrict__ x) {
    const int e = (blockIdx.x * blockDim.x + threadIdx.x) * 4;
    const float4 v4 = *(const float4*)&x[e];
    float v[4] = {v4.x, v4.y, v4.z, v4.w};
    __nv_bfloat16 hi[4], lo[4];
#pragma unroll
    for (int i = 0; i < 4; i++) {
        hi[i] = __float2bfloat16(v[i]);
        lo[i] = __float2bfloat16(v[i] - __bfloat162float(hi[i]));
    }
    *(uint2*)&g_x_hi[e] = *(uint2*)hi;
    *(uint2*)&g_x_lo[e] = *(uint2*)lo;
}

// ---------------- cp.async helper ----------------
__device__ __forceinline__ void cp16(void* s, const void* g) {
    unsigned sa = (unsigned)__cvta_generic_to_shared(s);
    asm volatile("cp.async.cg.shared.global [%0], [%1], 16;\n" :: "r"(sa), "l"(g));
}

// ---------------- pipelined bf16x3 GEMM body ----------------
// 256 threads = 8 warps (4 m-strips x 2 n-strips). Warp tile: 32 x (BN/2).
// MODE 0: write bf16 hi/lo split outputs (Chi/Clo).
// MODE 1: out = acc + sum_j cw[j]*coh[b,j,:], f32 output Cf.
template<int BN, int MODE>
__device__ __forceinline__ void gemm_body(
    const __nv_bfloat16* __restrict__ Ah, const __nv_bfloat16* __restrict__ Al,
    const __nv_bfloat16* __restrict__ Bh, const __nv_bfloat16* __restrict__ Bl,
    __nv_bfloat16* __restrict__ Chi, __nv_bfloat16* __restrict__ Clo,
    float* __restrict__ Cf, const float* __restrict__ coh,
    int Kdim, int Ndim)
{
    constexpr int APAD = BK + 8;           // 24 elems/row
    constexpr int BPAD = BN + 8;
    constexpr int AS_BYTES = 2 * 2 * BM * APAD * 2;
    constexpr int BS_BYTES = 2 * 2 * BK * BPAD * 2;
    constexpr int SM_BYTES = (AS_BYTES + BS_BYTES) > 32768 ? (AS_BYTES + BS_BYTES) : 32768;
    __shared__ __align__(16) unsigned char smem_raw[SM_BYTES];

    const int tid    = threadIdx.x;
    const int wid    = tid >> 5;
    const int lane   = tid & 31;
    const int warp_m = wid & 3;
    const int warp_n = wid >> 2;
    const int mBase  = blockIdx.y * BM;
    const int nBase  = blockIdx.x * BN;

    constexpr int W  = BN / 2;     // cols per warp
    constexpr int WN = BN / 32;    // n-tiles per warp

    auto sA = [&](int s, int h) -> __nv_bfloat16* {
        return (__nv_bfloat16*)smem_raw + (s * 2 + h) * BM * APAD;
    };
    auto sB = [&](int s, int h) -> __nv_bfloat16* {
        return (__nv_bfloat16*)(smem_raw + AS_BYTES) + (s * 2 + h) * BK * BPAD;
    };

    auto load_stage = [&](int stage, int kt) {
        const int k0 = kt * BK;
        {   // A: 128 rows x 16 cols = 256 x 16B chunks (hi + lo)
            const int r = tid >> 1;
            const int c = (tid & 1) * 8;
            const size_t go = (size_t)(mBase + r) * Kdim + k0 + c;
            cp16(sA(stage, 0) + r * APAD + c, Ah + go);
            cp16(sA(stage, 1) + r * APAD + c, Al + go);
        }
        {   // B: 16 rows x BN cols
            constexpr int CH = BN / 8;
            const int r = tid / CH;
            const int c = (tid % CH) * 8;
            if (r < BK) {
                const size_t go = (size_t)(k0 + r) * Ndim + nBase + c;
                cp16(sB(stage, 0) + r * BPAD + c, Bh + go);
                cp16(sB(stage, 1) + r * BPAD + c, Bl + go);
            }
        }
        asm volatile("cp.async.commit_group;\n");
    };

    wmma::fragment<wmma::accumulator, 16, 16, 16, float> acc[2][WN];
#pragma unroll
    for (int mi = 0; mi < 2; mi++)
#pragma unroll
        for (int ni = 0; ni < WN; ni++) wmma::fill_fragment(acc[mi][ni], 0.0f);

    const int NT = Kdim / BK;
    load_stage(0, 0);

    for (int it = 0; it < NT; ++it) {
        asm volatile("cp.async.wait_group 0;\n");
        __syncthreads();
        if (it + 1 < NT) load_stage((it + 1) & 1, it + 1);

        const int s = it & 1;
        wmma::fragment<wmma::matrix_a, 16, 16, 16, __nv_bfloat16, wmma::row_major> fa_h[2], fa_l[2];
#pragma unroll
        for (int mi = 0; mi < 2; mi++) {
            const int row = warp_m * 32 + mi * 16;
            wmma::load_matrix_sync(fa_h[mi], sA(s, 0) + row * APAD, APAD);
            wmma::load_matrix_sync(fa_l[mi], sA(s, 1) + row * APAD, APAD);
        }
#pragma unroll
        for (int ni = 0; ni < WN; ni++) {
            const int col = warp_n * W + ni * 16;
            wmma::fragment<wmma::matrix_b, 16, 16, 16, __nv_bfloat16, wmma::row_major> fb_h, fb_l;
            wmma::load_matrix_sync(fb_h, sB(s, 0) + col, BPAD);
            wmma::load_matrix_sync(fb_l, sB(s, 1) + col, BPAD);
#pragma unroll
            for (int mi = 0; mi < 2; mi++) {
                wmma::mma_sync(acc[mi][ni], fa_h[mi], fb_h, acc[mi][ni]);
                wmma::mma_sync(acc[mi][ni], fa_h[mi], fb_l, acc[mi][ni]);
                wmma::mma_sync(acc[mi][ni], fa_l[mi], fb_h, acc[mi][ni]);
            }
        }
    }

    // ---------------- epilogue (smem staging, per-warp private region) ----------------
    __syncthreads();
    float* wbuf = (float*)smem_raw + wid * 1024;

    float cw[NP];
    if (MODE == 1) {
#pragma unroll
        for (int j = 0; j < NP; j++) cw[j] = g_cw[j];
    }

#pragma unroll
    for (int mi = 0; mi < 2; mi++) {
#pragma unroll
        for (int ni = 0; ni < WN; ni++)
            wmma::store_matrix_sync(wbuf + ni * 16, acc[mi][ni], W, wmma::mem_row_major);
        __syncwarp();

        const int r  = lane >> 1;                 // 0..15
        const int c0 = (lane & 1) * (W / 2);      // half-row per lane
        const int g_r = mBase + warp_m * 32 + mi * 16 + r;
        const int g_c = nBase + warp_n * W + c0;

        if (MODE == 0) {
#pragma unroll
            for (int i = 0; i < W / 2; i++) {
                float v = wbuf[r * W + c0 + i];
                __nv_bfloat16 h = __float2bfloat16(v);
                Chi[(size_t)g_r * Ndim + g_c + i] = h;
                Clo[(size_t)g_r * Ndim + g_c + i] = __float2bfloat16(v - __bfloat162float(h));
            }
        } else {
#pragma unroll
            for (int i = 0; i < W / 2; i += 4) {
                float4 v = *(float4*)&wbuf[r * W + c0 + i];
                const int hcol = g_c + i;
#pragma unroll
                for (int j = 0; j < NP; j++) {
                    const float4 cc = *(const float4*)&coh[((size_t)g_r * NP + j) * HD + hcol];
                    v.x = fmaf(cw[j], cc.x, v.x);
                    v.y = fmaf(cw[j], cc.y, v.y);
                    v.z = fmaf(cw[j], cc.z, v.z);
                    v.w = fmaf(cw[j], cc.w, v.w);
                }
                *(float4*)&Cf[(size_t)g_r * HD + hcol] = v;
            }
        }
        __syncwarp();
    }
}

// ---------------- GEMM entry points: globals bound in DEVICE code ----------------
// (passing __device__ symbols as kernel args from host is UB — on GB300's ATS
//  path it silently reads the zero host shadow; that was the R3 bug)

// GEMM 1: M = W_input @ W_eff  (1024x1024x1024), BN=64
__global__ void __launch_bounds__(256) gemm1_kernel() {
    gemm_body<64, 0>(g_Wi_hi, g_Wi_lo, g_We_hi, g_We_lo,
                     g_M_hi, g_M_lo, nullptr, nullptr, HD, HD);
}

// GEMM 2: out = x @ M + coherent  (2048x1024x1024), BN=128
__global__ void __launch_bounds__(256) gemm2_kernel(float* __restrict__ Cf,
                                                    const float* __restrict__ coh) {
    gemm_body<128, 1>(g_x_hi, g_x_lo, g_M_hi, g_M_lo,
                      nullptr, nullptr, Cf, coh, HD, HD);
}

// ---------------- launch ----------------
extern "C" void kernel_launch(void* const* d_in, const int* in_sizes, int n_in,
                              void* d_out, int out_size) {
    (void)in_sizes; (void)n_in; (void)out_size;
    const float* x   = (const float*)d_in[0];
    const float* Wi  = (const float*)d_in[1];
    const float* Wp  = (const float*)d_in[2];
    const float* J   = (const float*)d_in[3];
    const float* coh = (const float*)d_in[4];
    const float* t   = (const float*)d_in[5];
    float* out = (float*)d_out;

    prep_kernel<<<1, 32>>>(J, t);
    build_weff_kernel<<<(HD * HD / 4) / 256, 256>>>(Wp, Wi);
    split_x_kernel<<<(BD * HD / 4) / 256, 256>>>(x);

    {
        dim3 g(HD / 64, HD / BM);       // 16 x 8 = 128 CTAs
        gemm1_kernel<<<g, 256>>>();
    }
    {
        dim3 g(HD / 128, BD / BM);      // 8 x 16 = 128 CTAs
        gemm2_kernel<<<g, 256>>>(out, coh);
    }
}

// round 7
// speedup vs baseline: 1.2688x; 1.2230x over previous
#include <cuda_runtime.h>
#include <cuda_bf16.h>
#include <mma.h>
#include <cstdint>

using namespace nvcuda;

#define NP 8
#define HD 1024
#define BD 2048
#define BM 128
#define BK 32
#define NT 32            // 1024 / BK
#define APITCH 40        // 32 + 8 elems (80B rows: 8 distinct 128B phases)

// ---------------- device scratch ----------------
__device__ float g_v[NP];    // (1-alpha)*u[j]
__device__ float g_cw[NP];   // alpha*u[j]

__device__ __nv_bfloat16 g_Wi_hi[HD * HD];   // A1: W_input [m,k]
__device__ __nv_bfloat16 g_Wi_lo[HD * HD];
__device__ __nv_bfloat16 g_We_hi[HD * HD];   // B1: W_eff   [k,n]
__device__ __nv_bfloat16 g_We_lo[HD * HD];
__device__ __nv_bfloat16 g_M_hi[HD * HD];    // B2: M       [k,n]
__device__ __nv_bfloat16 g_M_lo[HD * HD];
__device__ __nv_bfloat16 g_x_hi[BD * HD];    // A2: x       [b,k]
__device__ __nv_bfloat16 g_x_lo[BD * HD];

// ---------------- kernel 1: scalars ----------------
__global__ void prep_kernel(const float* __restrict__ J, const float* __restrict__ t_ptr) {
    if (threadIdx.x != 0) return;
    const float t = t_ptr[0];
    float alpha = expf(-t / 51.0f);
    alpha = fminf(fmaxf(alpha, 0.0f), 1.0f);
    const float phase = 2.0f * 3.14159265358979323846f * 20.0f * t / 1000.0f;
    float colsum[NP];
#pragma unroll
    for (int j = 0; j < NP; j++) colsum[j] = 0.0f;
    for (int i = 0; i < NP; i++) {
        float row[NP];
        float mx = -1e30f;
#pragma unroll
        for (int j = 0; j < NP; j++) {
            float js = 0.5f * (J[i * NP + j] + J[j * NP + i]);
            row[j] = cosf(phase * js);
            mx = fmaxf(mx, row[j]);
        }
        float s = 0.0f;
#pragma unroll
        for (int j = 0; j < NP; j++) { row[j] = expf(row[j] - mx); s += row[j]; }
        float inv_s = 1.0f / s;
#pragma unroll
        for (int j = 0; j < NP; j++) colsum[j] += row[j] * inv_s;
    }
    const float scale = alpha / (float)(NP * NP);
#pragma unroll
    for (int j = 0; j < NP; j++) {
        float u = scale * colsum[j];
        g_v[j]  = (1.0f - alpha) * u;
        g_cw[j] = alpha * u;
    }
}

// ---------------- kernel 2: W_eff build + split, and W_input split ----------------
__global__ void build_weff_kernel(const float* __restrict__ Wp, const float* __restrict__ Wi) {
    const int e = (blockIdx.x * blockDim.x + threadIdx.x) * 4;
    float4 s = make_float4(0.f, 0.f, 0.f, 0.f);
#pragma unroll
    for (int j = 0; j < NP; j++) {
        const float4 w = *(const float4*)&Wp[(size_t)j * (HD * HD) + e];
        const float v = g_v[j];
        s.x = fmaf(v, w.x, s.x); s.y = fmaf(v, w.y, s.y);
        s.z = fmaf(v, w.z, s.z); s.w = fmaf(v, w.w, s.w);
    }
    __nv_bfloat16 hi[4], lo[4];
    float sv[4] = {s.x, s.y, s.z, s.w};
#pragma unroll
    for (int i = 0; i < 4; i++) {
        hi[i] = __float2bfloat16(sv[i]);
        lo[i] = __float2bfloat16(sv[i] - __bfloat162float(hi[i]));
    }
    *(uint2*)&g_We_hi[e] = *(uint2*)hi;
    *(uint2*)&g_We_lo[e] = *(uint2*)lo;

    const float4 w = *(const float4*)&Wi[e];
    float wv[4] = {w.x, w.y, w.z, w.w};
#pragma unroll
    for (int i = 0; i < 4; i++) {
        hi[i] = __float2bfloat16(wv[i]);
        lo[i] = __float2bfloat16(wv[i] - __bfloat162float(hi[i]));
    }
    *(uint2*)&g_Wi_hi[e] = *(uint2*)hi;
    *(uint2*)&g_Wi_lo[e] = *(uint2*)lo;
}

// ---------------- kernel 3: split x ----------------
__global__ void split_x_kernel(const float* __restrict__ x) {
    const int e = (blockIdx.x * blockDim.x + threadIdx.x) * 4;
    const float4 v4 = *(const float4*)&x[e];
    float v[4] = {v4.x, v4.y, v4.z, v4.w};
    __nv_bfloat16 hi[4], lo[4];
#pragma unroll
    for (int i = 0; i < 4; i++) {
        hi[i] = __float2bfloat16(v[i]);
        lo[i] = __float2bfloat16(v[i] - __bfloat162float(hi[i]));
    }
    *(uint2*)&g_x_hi[e] = *(uint2*)hi;
    *(uint2*)&g_x_lo[e] = *(uint2*)lo;
}

// ---------------- cp.async helper ----------------
__device__ __forceinline__ void cp16(void* s, const void* g) {
    unsigned sa = (unsigned)__cvta_generic_to_shared(s);
    asm volatile("cp.async.cg.shared.global [%0], [%1], 16;\n" :: "r"(sa), "l"(g));
}
#define CP_COMMIT() asm volatile("cp.async.commit_group;\n")
#define CP_WAIT1()  asm volatile("cp.async.wait_group 1;\n")
#define CP_WAIT0()  asm volatile("cp.async.wait_group 0;\n")

// ---------------- 3-stage pipelined bf16x3 HMMA GEMM ----------------
// NWN warps in n (threads = NWN*128), 4 warps in m. Warp tile 32x32 (2x2 wmma).
// MODE 0: write bf16 hi/lo split (Chi/Clo). MODE 1: out = acc + sum_j cw[j]*coh.
template<int BN, int NWN, int MODE>
__device__ __forceinline__ void gemm_body(
    const __nv_bfloat16* __restrict__ Ah, const __nv_bfloat16* __restrict__ Al,
    const __nv_bfloat16* __restrict__ Bh, const __nv_bfloat16* __restrict__ Bl,
    __nv_bfloat16* __restrict__ Chi, __nv_bfloat16* __restrict__ Clo,
    float* __restrict__ Cf, const float* __restrict__ coh)
{
    constexpr int T       = NWN * 128;
    constexpr int BPITCH  = BN + 8;
    constexpr int A_ONE   = BM * APITCH * 2;        // bytes, one of {hi,lo}
    constexpr int B_ONE   = BK * BPITCH * 2;
    constexpr int OFF_AL  = A_ONE;
    constexpr int OFF_BH  = 2 * A_ONE;
    constexpr int OFF_BL  = 2 * A_ONE + B_ONE;
    constexpr int STAGE   = 2 * A_ONE + 2 * B_ONE;

    extern __shared__ __align__(16) unsigned char smem[];

    const int tid    = threadIdx.x;
    const int wid    = tid >> 5;
    const int lane   = tid & 31;
    const int warp_m = wid & 3;        // 0..3 -> 32-row strip
    const int warp_n = wid >> 2;       // 0..NWN-1 -> 32-col strip
    const int mBase  = blockIdx.y * BM;
    const int nBase  = blockIdx.x * BN;

    auto load_stage = [&](int s, int kt) {
        const int k0 = kt * BK;
        unsigned char* st = smem + s * STAGE;
        // A: 128 rows x 32 cols -> 512 x 16B chunks each for hi and lo
#pragma unroll
        for (int i = 0; i < 512 / T; i++) {
            const int c   = tid + i * T;
            const int row = c >> 2;
            const int ch  = c & 3;
            const int off = row * (APITCH * 2) + ch * 16;
            const size_t go = (size_t)(mBase + row) * HD + k0 + ch * 8;
            cp16(st + off,          Ah + go);
            cp16(st + OFF_AL + off, Al + go);
        }
        // B: 32 rows x BN cols
        constexpr int CH = BN / 8;
#pragma unroll
        for (int i = 0; i < (BK * CH) / T; i++) {
            const int c   = tid + i * T;
            const int row = c / CH;
            const int ch  = c % CH;
            const int off = row * (BPITCH * 2) + ch * 16;
            const size_t go = (size_t)(k0 + row) * HD + nBase + ch * 8;
            cp16(st + OFF_BH + off, Bh + go);
            cp16(st + OFF_BL + off, Bl + go);
        }
        CP_COMMIT();
    };

    wmma::fragment<wmma::accumulator, 16, 16, 16, float> acc[2][2];
#pragma unroll
    for (int mi = 0; mi < 2; mi++)
#pragma unroll
        for (int ni = 0; ni < 2; ni++) wmma::fill_fragment(acc[mi][ni], 0.0f);

    load_stage(0, 0);
    load_stage(1, 1);

    for (int it = 0; it < NT; ++it) {
        if (it + 1 < NT) CP_WAIT1(); else CP_WAIT0();
        __syncthreads();
        if (it + 2 < NT) load_stage((it + 2) % 3, it + 2);

        const unsigned char* st = smem + (it % 3) * STAGE;
        const __nv_bfloat16* pAh = (const __nv_bfloat16*)(st);
        const __nv_bfloat16* pAl = (const __nv_bfloat16*)(st + OFF_AL);
        const __nv_bfloat16* pBh = (const __nv_bfloat16*)(st + OFF_BH);
        const __nv_bfloat16* pBl = (const __nv_bfloat16*)(st + OFF_BL);

#pragma unroll
        for (int kc = 0; kc < 2; kc++) {
            wmma::fragment<wmma::matrix_a, 16, 16, 16, __nv_bfloat16, wmma::row_major> fa_h[2], fa_l[2];
            wmma::fragment<wmma::matrix_b, 16, 16, 16, __nv_bfloat16, wmma::row_major> fb_h[2], fb_l[2];
#pragma unroll
            for (int mi = 0; mi < 2; mi++) {
                const int row = warp_m * 32 + mi * 16;
                wmma::load_matrix_sync(fa_h[mi], pAh + row * APITCH + kc * 16, APITCH);
                wmma::load_matrix_sync(fa_l[mi], pAl + row * APITCH + kc * 16, APITCH);
            }
#pragma unroll
            for (int ni = 0; ni < 2; ni++) {
                const int col = warp_n * 32 + ni * 16;
                wmma::load_matrix_sync(fb_h[ni], pBh + (kc * 16) * BPITCH + col, BPITCH);
                wmma::load_matrix_sync(fb_l[ni], pBl + (kc * 16) * BPITCH + col, BPITCH);
            }
            // pass-major ordering: dependent acc reuse is 4 MMAs apart
#pragma unroll
            for (int mi = 0; mi < 2; mi++)
#pragma unroll
                for (int ni = 0; ni < 2; ni++)
                    wmma::mma_sync(acc[mi][ni], fa_h[mi], fb_h[ni], acc[mi][ni]);
#pragma unroll
            for (int mi = 0; mi < 2; mi++)
#pragma unroll
                for (int ni = 0; ni < 2; ni++)
                    wmma::mma_sync(acc[mi][ni], fa_h[mi], fb_l[ni], acc[mi][ni]);
#pragma unroll
            for (int mi = 0; mi < 2; mi++)
#pragma unroll
                for (int ni = 0; ni < 2; ni++)
                    wmma::mma_sync(acc[mi][ni], fa_l[mi], fb_h[ni], acc[mi][ni]);
        }
    }

    // ---------------- epilogue (per-warp 16x32 f32 staging buffer) ----------------
    __syncthreads();
    float* buf = (float*)smem + wid * 512;

    float cw[NP];
    if (MODE == 1) {
#pragma unroll
        for (int j = 0; j < NP; j++) cw[j] = g_cw[j];
    }

#pragma unroll
    for (int mi = 0; mi < 2; mi++) {
#pragma unroll
        for (int ni = 0; ni < 2; ni++)
            wmma::store_matrix_sync(buf + ni * 16, acc[mi][ni], 32, wmma::mem_row_major);
        __syncwarp();

        if (MODE == 0) {
            const int r  = lane >> 1;            // 0..15
            const int c0 = (lane & 1) * 16;
            const int g_r = mBase + warp_m * 32 + mi * 16 + r;
            const int g_c = nBase + warp_n * 32 + c0;
            __nv_bfloat16 hi[16], lo[16];
#pragma unroll
            for (int i = 0; i < 16; i++) {
                const float v = buf[r * 32 + c0 + i];
                hi[i] = __float2bfloat16(v);
                lo[i] = __float2bfloat16(v - __bfloat162float(hi[i]));
            }
            const size_t ob = (size_t)g_r * HD + g_c;
            *(uint4*)&Chi[ob]     = *(uint4*)&hi[0];
            *(uint4*)&Chi[ob + 8] = *(uint4*)&hi[8];
            *(uint4*)&Clo[ob]     = *(uint4*)&lo[0];
            *(uint4*)&Clo[ob + 8] = *(uint4*)&lo[8];
        } else {
#pragma unroll
            for (int p = 0; p < 4; p++) {
                const int idx = p * 128 + lane * 4;
                const int r   = idx >> 5;
                const int c   = idx & 31;
                float4 v = *(float4*)&buf[r * 32 + c];
                const int b   = mBase + warp_m * 32 + mi * 16 + r;
                const int col = nBase + warp_n * 32 + c;
#pragma unroll
                for (int j = 0; j < NP; j++) {
                    const float4 cc = *(const float4*)&coh[((size_t)b * NP + j) * HD + col];
                    v.x = fmaf(cw[j], cc.x, v.x);
                    v.y = fmaf(cw[j], cc.y, v.y);
                    v.z = fmaf(cw[j], cc.z, v.z);
                    v.w = fmaf(cw[j], cc.w, v.w);
                }
                *(float4*)&Cf[(size_t)b * HD + col] = v;
            }
        }
        __syncwarp();
    }
}

// ---------------- entry points (globals bound in device code) ----------------
__global__ void __launch_bounds__(256) gemm1_kernel() {
    gemm_body<64, 2, 0>(g_Wi_hi, g_Wi_lo, g_We_hi, g_We_lo,
                        g_M_hi, g_M_lo, nullptr, nullptr);
}
__global__ void __launch_bounds__(512) gemm2_kernel(float* __restrict__ Cf,
                                                    const float* __restrict__ coh) {
    gemm_body<128, 4, 1>(g_x_hi, g_x_lo, g_M_hi, g_M_lo,
                         nullptr, nullptr, Cf, coh);
}

// smem sizes: STAGE = 2*(128*40*2) + 2*(32*(BN+8)*2); 3 stages
#define SM1 (3 * (2 * (BM * APITCH * 2) + 2 * (BK * (64 + 8) * 2)))    // 89088
#define SM2 (3 * (2 * (BM * APITCH * 2) + 2 * (BK * (128 + 8) * 2)))   // 113664

// ---------------- launch ----------------
extern "C" void kernel_launch(void* const* d_in, const int* in_sizes, int n_in,
                              void* d_out, int out_size) {
    (void)in_sizes; (void)n_in; (void)out_size;
    const float* x   = (const float*)d_in[0];
    const float* Wi  = (const float*)d_in[1];
    const float* Wp  = (const float*)d_in[2];
    const float* J   = (const float*)d_in[3];
    const float* coh = (const float*)d_in[4];
    const float* t   = (const float*)d_in[5];
    float* out = (float*)d_out;

    cudaFuncSetAttribute(gemm1_kernel, cudaFuncAttributeMaxDynamicSharedMemorySize, SM1);
    cudaFuncSetAttribute(gemm2_kernel, cudaFuncAttributeMaxDynamicSharedMemorySize, SM2);

    prep_kernel<<<1, 32>>>(J, t);
    build_weff_kernel<<<(HD * HD / 4) / 256, 256>>>(Wp, Wi);
    split_x_kernel<<<(BD * HD / 4) / 256, 256>>>(x);

    {   // GEMM1: M = Wi @ We   grid 16 x 8 = 128 CTAs, 256 thr
        dim3 g(HD / 64, HD / BM);
        gemm1_kernel<<<g, 256, SM1>>>();
    }
    {   // GEMM2: out = x @ M + coherent   grid 8 x 16 = 128 CTAs, 512 thr
        dim3 g(HD / 128, BD / BM);
        gemm2_kernel<<<g, 512, SM2>>>(out, coh);
    }
}